// round 12
// baseline (speedup 1.0000x reference)
#include <cuda_runtime.h>
#include <math.h>

#define HSZ 1024
#define WSZ 1024
#define NIMG 12            // B*C = 4*3
#define TILE 64            // output tile (64x64), 512 threads
#define NPIX (NIMG * HSZ * WSZ)

// Scratch (static __device__ arrays = allowed):
//   g_x4: pointwise-processed image (after brightness/contrast)
//   g_h1: horizontal 15-tap blur of g_x4 (first half of blur1)
__device__ float g_x4[NPIX];
__device__ float g_h1[NPIX];

// ---------------------------------------------------------------------------
// Compile-time Gaussian weights (KSIZE=15, SIGMA=3) -> FFMA-imm literals.
// ---------------------------------------------------------------------------
__host__ __device__ constexpr double cexp_(double x) {
    double t = 1.0, s = 1.0;
    for (int i = 1; i < 60; ++i) { t *= x / i; s += t; }
    return s;
}
__host__ __device__ constexpr double gsum_() {
    double s = 0.0;
    for (int i = 0; i < 15; ++i) { double d = i - 7; s += cexp_(-d * d / 18.0); }
    return s;
}
__host__ __device__ constexpr float gw_(int k) {
    double d = k - 7; return (float)(cexp_(-d * d / 18.0) / gsum_());
}
#define GWDECL constexpr float GW[15] = {gw_(0), gw_(1), gw_(2),  gw_(3),  gw_(4),  \
    gw_(5),  gw_(6), gw_(7), gw_(8), gw_(9), gw_(10), gw_(11), gw_(12), gw_(13), gw_(14)}

__device__ __forceinline__ float tanh_approx(float x) {
    float y; asm("tanh.approx.f32 %0, %1;" : "=f"(y) : "f"(x));
    return y;
}

// ---------------------------------------------------------------------------
// K1: pointwise chain + horizontal blur H1, one block per image row.
//   - 256 threads x 4 px (float4)
//   - pointwise result -> g_x4 and smem row buffer (halo +-7 zero = row pad)
//   - 15-tap row blur from aligned LDS.128 windows -> g_h1
// ---------------------------------------------------------------------------
__global__ __launch_bounds__(256) void pointwise_h1_kernel(
    const float* __restrict__ x, const float* __restrict__ gains,
    const float* __restrict__ p_gamma, const float* __restrict__ p_sb,
    const float* __restrict__ p_hr, const float* __restrict__ p_br,
    const float* __restrict__ p_ct)
{
    GWDECL;
    __shared__ __align__(16) float sRow[1040];   // [8 zero | 1024 px | 8 zero]

    const int bx  = blockIdx.x;                  // img*1024 + row
    const int tid = threadIdx.x;
    const int ch  = (bx >> 10) % 3;

    const float gain = gains[ch];
    const float gam  = p_gamma[0];
    const float sbv  = p_sb[0], hrv = p_hr[0];
    const float shc  = -(sbv + hrv);
    const float brv  = p_br[0], ctv = p_ct[0];
    const float bc0  = 0.5f + brv;

    if (tid < 8) { sRow[tid] = 0.f; sRow[1032 + tid] = 0.f; }

    const int idx4 = bx * 256 + tid;             // float4 index (row-contiguous)
    float4 v4 = __ldg((const float4*)x + idx4);
    float* v = &v4.x;
    #pragma unroll
    for (int i = 0; i < 4; ++i) {
        float t = __powf(v[i] * gain, gam);                   // WB + gamma
        float hi = fmaf(tanh_approx((t - 0.5f) * 5.f), 0.5f, 0.5f);
        t = fmaf(shc, hi, t + sbv);                           // shadow/highlight
        t = fminf(fmaxf(t, 0.f), 1.f);
        t = fmaf(ctv, t - 0.5f, bc0);                         // brightness/contrast
        v[i] = fminf(fmaxf(t, 0.f), 1.f);
    }
    ((float4*)g_x4)[idx4] = v4;
    *(float4*)&sRow[8 + 4 * tid] = v4;
    __syncthreads();

    // window w[0..19] = sRow floats [4t .. 4t+19] = x4 cols [4t-8 .. 4t+11]
    float w[20];
    const float4* sv = (const float4*)sRow;
    #pragma unroll
    for (int i = 0; i < 5; ++i) {
        float4 q = sv[tid + i];                  // conflict-free LDS.128
        w[4 * i + 0] = q.x; w[4 * i + 1] = q.y;
        w[4 * i + 2] = q.z; w[4 * i + 3] = q.w;
    }
    float4 o; float* op = &o.x;
    #pragma unroll
    for (int j = 0; j < 4; ++j) {                // out col c = 4t+j needs x4[c-7..c+7] = w[j+1..j+15]
        float a = 0.f;
        #pragma unroll
        for (int k = 0; k < 15; ++k) a = fmaf(w[j + 1 + k], GW[k], a);
        op[j] = a;
    }
    ((float4*)g_h1)[idx4] = o;
}

// ---------------------------------------------------------------------------
// K2: remaining cascade per 64x64 tile. 512 threads, smem 55,080 B ->
// 4 CTAs/SM (64 warps). Buffers: sB (92x81) then sD (78x67) aliased on it;
// sC (78x81) separate.
//   phase0: copy g_h1 halo [92 rows x 78 cols] -> sB (zero outside image)
//   V1+LCE: sB -> sC [78x78]; LCE centers read coalesced from g_x4
//   H2: sC -> sD [78x64]   (row-fast lanes, conflict-free: 81%32=17)
//   V2+softness+mask -> out
// ---------------------------------------------------------------------------
__global__ __launch_bounds__(512, 4) void blur_kernel(
    const float* __restrict__ p_ea, const float* __restrict__ p_soft,
    const float* __restrict__ p_int, const float* __restrict__ p_rot,
    const float* __restrict__ p_hard, float* __restrict__ out)
{
    GWDECL;
    extern __shared__ float smem[];
    float* const sB = smem;                 // 92*81 = 7452
    float* const sD = smem;                 // 78*67 = 5226 (alias; sB dead after V1)
    float* const sC = smem + 7452;          // 78*81 = 6318

    const int tid = threadIdx.x;
    const int img = blockIdx.z;
    const int ty0 = blockIdx.y * TILE;
    const int tx0 = blockIdx.x * TILE;

    const float eav = p_ea[0], sof = p_soft[0];
    const float itn = p_int[0], hrd = p_hard[0];
    float snt, cst;
    sincosf(p_rot[0] * 0.017453292519943295f, &snt, &cst);

    const float* __restrict__ xin = g_x4 + (size_t)img * (HSZ * WSZ);
    const float* __restrict__ hin = g_h1 + (size_t)img * (HSZ * WSZ);
    // needs rows ty0-14..ty0+77, cols tx0-7..tx0+70
    const bool interior = (ty0 >= 14) && (ty0 + 78 <= HSZ) && (tx0 >= 7) && (tx0 + 71 <= WSZ);

    // ---- phase 0: coalesced copy of H1 halo -> sB ----
    if (interior) {
        const float* __restrict__ base = hin + (ty0 - 14) * WSZ + (tx0 - 7);
        for (int p = tid; p < 92 * 78; p += 512) {
            int r = p / 78, c = p - r * 78;
            sB[r * 81 + c] = __ldg(base + r * WSZ + c);
        }
    } else {
        for (int p = tid; p < 92 * 78; p += 512) {
            int r = p / 78, c = p - r * 78;
            int gy = ty0 - 14 + r, gx = tx0 - 7 + c;
            float v = 0.f;
            if ((unsigned)gy < HSZ && (unsigned)gx < WSZ) v = __ldg(hin + gy * WSZ + gx);
            sB[r * 81 + c] = v;                 // H1 == 0 outside image (zero-pad)
        }
    }
    __syncthreads();

    // ---- V1 + LCE epilogue: sB -> sC. 468 thr: col=tid%78, 6 strips x 13 rows ----
    if (tid < 468) {
        int strip = tid / 78, ccol = tid - 78 * strip;
        int r0 = strip * 13;
        const float* b = &sB[r0 * 81 + ccol];
        float acc[13] = {};
        #pragma unroll
        for (int i = 0; i < 27; ++i) {          // rows r0..r0+26 <= 91, all real
            float v = b[i * 81];
            #pragma unroll
            for (int k = 0; k < 15; ++k) {
                int j = i - k;
                if (j >= 0 && j < 13) acc[j] = fmaf(v, GW[k], acc[j]);
            }
        }
        if (interior) {
            const float* __restrict__ ctr = xin + (ty0 - 7 + r0) * WSZ + (tx0 - 7 + ccol);
            #pragma unroll
            for (int j = 0; j < 13; ++j) {
                float a = __ldg(ctr + j * WSZ); // coalesced: lanes = consecutive cols
                sC[(r0 + j) * 81 + ccol] = fmaf(eav, a - acc[j], a);  // x + ea*(x - mean)
            }
        } else {
            #pragma unroll
            for (int j = 0; j < 13; ++j) {
                int rr = r0 + j;
                int gy = ty0 - 7 + rr, gx = tx0 - 7 + ccol;
                float val = 0.f;
                if ((unsigned)gy < HSZ && (unsigned)gx < WSZ) {
                    float a = __ldg(xin + gy * WSZ + gx);
                    val = fmaf(eav, a - acc[j], a);
                }
                sC[rr * 81 + ccol] = val;       // zero outside image = blur2 zero-pad
            }
        }
    }
    __syncthreads();

    // ---- H2: sC -> sD (aliases sB). row-fast lanes, 11 outputs/thread, window 25 ----
    if (tid < 468) {
        int r = tid % 78, seg = tid / 78;
        int c0 = seg * 11;
        const float* c = &sC[r * 81 + c0];
        float acc[11] = {};
        #pragma unroll
        for (int i = 0; i < 25; ++i) {
            float v = c[i];                     // junk cols 78..79 -> only discarded accs
            #pragma unroll
            for (int k = 0; k < 15; ++k) {
                int j = i - k;
                if (j >= 0 && j < 11) acc[j] = fmaf(v, GW[k], acc[j]);
            }
        }
        float* d = &sD[r * 67 + c0];
        #pragma unroll
        for (int j = 0; j < 11; ++j)
            if (c0 + j < 64) d[j] = acc[j];
    }
    __syncthreads();

    // ---- V2 + softness + gradient mask -> out. 64 cols x 8 strips x 8 rows ----
    {
        int strip = tid >> 6, cc = tid & 63;
        int r0 = strip * 8;
        const float* d = &sD[r0 * 67 + cc];
        float acc[8] = {};
        #pragma unroll
        for (int i = 0; i < 22; ++i) {          // rows r0..r0+21 <= 77, all real
            float v = d[i * 67];
            #pragma unroll
            for (int k = 0; k < 15; ++k) {
                int j = i - k;
                if (j >= 0 && j < 8) acc[j] = fmaf(v, GW[k], acc[j]);
            }
        }
        float* __restrict__ op = out + (size_t)img * (HSZ * WSZ);
        const float yscale = 2.f / (float)(HSZ - 1);
        const float xscale = 2.f / (float)(WSZ - 1);
        const float mc = 1.f - 0.5f * itn;      // factor = mc + md*tanh(-hrd*gr/2)
        const float md = -0.5f * itn;
        const int gx = tx0 + cc;
        const float xn = fmaf((float)gx, xscale, -1.f);
        #pragma unroll
        for (int j = 0; j < 8; ++j) {
            int gy = ty0 + r0 + j;
            float x5c = sC[(r0 + j + 7) * 81 + cc + 7];
            float v = sof * acc[j] + (1.f - sof) * x5c;        // softness blend
            float yn = fmaf((float)gy, yscale, -1.f);
            float gr = xn * cst + yn * snt;
            float fac = fmaf(md, tanh_approx(-0.5f * hrd * gr), mc);  // 1 - itn*sigmoid(-hrd*gr)
            v = fminf(fmaxf(v * fac, 0.f), 1.f);
            op[gy * WSZ + gx] = v;
        }
    }
}

extern "C" void kernel_launch(void* const* d_in, const int* in_sizes, int n_in,
                              void* d_out, int out_size) {
    (void)in_sizes; (void)n_in; (void)out_size;

    static const int SMEM_BYTES = (7452 + 6318) * 4;          // 55,080
    cudaFuncSetAttribute(blur_kernel, cudaFuncAttributeMaxDynamicSharedMemorySize, SMEM_BYTES);

    pointwise_h1_kernel<<<NIMG * HSZ, 256>>>(                 // one block per image row
        (const float*)d_in[0],  // x
        (const float*)d_in[1],  // gains
        (const float*)d_in[2],  // gamma
        (const float*)d_in[3],  // shadow_boost
        (const float*)d_in[4],  // highlight_reduce
        (const float*)d_in[5],  // brightness
        (const float*)d_in[6]); // contrast

    dim3 grid(WSZ / TILE, HSZ / TILE, NIMG);                  // 16 x 16 x 12 = 3072 CTAs
    blur_kernel<<<grid, 512, SMEM_BYTES>>>(
        (const float*)d_in[7],  // enhance_amount
        (const float*)d_in[8],  // softness
        (const float*)d_in[9],  // intensity
        (const float*)d_in[10], // rotation
        (const float*)d_in[11], // hardness
        (float*)d_out);
}

// round 13
// speedup vs baseline: 1.0571x; 1.0571x over previous
#include <cuda_runtime.h>
#include <cuda_fp16.h>
#include <math.h>

#define HSZ 1024
#define WSZ 1024
#define NIMG 12            // B*C = 4*3
#define TILE 64            // output tile (64x64), 512 threads
#define NPIX (NIMG * HSZ * WSZ)

// Scratch (static __device__ arrays = allowed):
//   g_x4:  pointwise-processed image (fp32, exact path for LCE centers)
//   g_h1h: horizontal 15-tap blur of g_x4 (fp16: halves L2 footprint so the
//          K2 working set x4+h1+out = 120MB fits the 126MB L2)
__device__ float  g_x4[NPIX];
__device__ __half g_h1h[NPIX];

// ---------------------------------------------------------------------------
// Compile-time Gaussian weights (KSIZE=15, SIGMA=3) -> FFMA-imm literals.
// ---------------------------------------------------------------------------
__host__ __device__ constexpr double cexp_(double x) {
    double t = 1.0, s = 1.0;
    for (int i = 1; i < 60; ++i) { t *= x / i; s += t; }
    return s;
}
__host__ __device__ constexpr double gsum_() {
    double s = 0.0;
    for (int i = 0; i < 15; ++i) { double d = i - 7; s += cexp_(-d * d / 18.0); }
    return s;
}
__host__ __device__ constexpr float gw_(int k) {
    double d = k - 7; return (float)(cexp_(-d * d / 18.0) / gsum_());
}
#define GWDECL constexpr float GW[15] = {gw_(0), gw_(1), gw_(2),  gw_(3),  gw_(4),  \
    gw_(5),  gw_(6), gw_(7), gw_(8), gw_(9), gw_(10), gw_(11), gw_(12), gw_(13), gw_(14)}

__device__ __forceinline__ float tanh_approx(float x) {
    float y; asm("tanh.approx.f32 %0, %1;" : "=f"(y) : "f"(x));
    return y;
}

// ---------------------------------------------------------------------------
// K1: pointwise chain + horizontal blur H1, one block per image row.
//   256 threads x 4 px (float4); x4 -> g_x4 (fp32) ; H1 -> g_h1h (fp16)
// ---------------------------------------------------------------------------
__global__ __launch_bounds__(256) void pointwise_h1_kernel(
    const float* __restrict__ x, const float* __restrict__ gains,
    const float* __restrict__ p_gamma, const float* __restrict__ p_sb,
    const float* __restrict__ p_hr, const float* __restrict__ p_br,
    const float* __restrict__ p_ct)
{
    GWDECL;
    __shared__ __align__(16) float sRow[1040];   // [8 zero | 1024 px | 8 zero]

    const int bx  = blockIdx.x;                  // img*1024 + row
    const int tid = threadIdx.x;
    const int ch  = (bx >> 10) % 3;

    const float gain = gains[ch];
    const float gam  = p_gamma[0];
    const float sbv  = p_sb[0], hrv = p_hr[0];
    const float shc  = -(sbv + hrv);
    const float brv  = p_br[0], ctv = p_ct[0];
    const float bc0  = 0.5f + brv;

    if (tid < 8) { sRow[tid] = 0.f; sRow[1032 + tid] = 0.f; }

    const int idx4 = bx * 256 + tid;             // float4 index (row-contiguous)
    float4 v4 = __ldg((const float4*)x + idx4);
    float* v = &v4.x;
    #pragma unroll
    for (int i = 0; i < 4; ++i) {
        float t = __powf(v[i] * gain, gam);                   // WB + gamma
        float hi = fmaf(tanh_approx((t - 0.5f) * 5.f), 0.5f, 0.5f);
        t = fmaf(shc, hi, t + sbv);                           // shadow/highlight
        t = fminf(fmaxf(t, 0.f), 1.f);
        t = fmaf(ctv, t - 0.5f, bc0);                         // brightness/contrast
        v[i] = fminf(fmaxf(t, 0.f), 1.f);
    }
    ((float4*)g_x4)[idx4] = v4;
    *(float4*)&sRow[8 + 4 * tid] = v4;
    __syncthreads();

    // window w[0..19] = sRow floats [4t .. 4t+19] = x4 cols [4t-8 .. 4t+11]
    float w[20];
    const float4* sv = (const float4*)sRow;
    #pragma unroll
    for (int i = 0; i < 5; ++i) {
        float4 q = sv[tid + i];                  // conflict-free LDS.128
        w[4 * i + 0] = q.x; w[4 * i + 1] = q.y;
        w[4 * i + 2] = q.z; w[4 * i + 3] = q.w;
    }
    float o[4];
    #pragma unroll
    for (int j = 0; j < 4; ++j) {                // out col c = 4t+j needs x4[c-7..c+7] = w[j+1..j+15]
        float a = 0.f;
        #pragma unroll
        for (int k = 0; k < 15; ++k) a = fmaf(w[j + 1 + k], GW[k], a);
        o[j] = a;
    }
    __half2 h0 = __floats2half2_rn(o[0], o[1]);
    __half2 h1 = __floats2half2_rn(o[2], o[3]);
    uint2 u;
    u.x = *reinterpret_cast<unsigned*>(&h0);
    u.y = *reinterpret_cast<unsigned*>(&h1);
    *reinterpret_cast<uint2*>(g_h1h + 4 * (size_t)idx4) = u;   // one STG.64
}

// ---------------------------------------------------------------------------
// K2: remaining cascade per 64x64 tile. 512 threads, smem 55,080 B ->
// 4 CTAs/SM (64 warps). Buffers: sB (92x81) then sD (78x67) aliased; sC (78x81).
//   phase0: copy g_h1h halo [92 x 78] -> sB (fp16->fp32; zero outside image)
//   V1+LCE: sB -> sC [78x78]; LCE centers read coalesced from g_x4 (fp32)
//   H2: sC -> sD [78x64]   (row-fast lanes, conflict-free: 81%32=17)
//   V2+softness+mask -> out
// ---------------------------------------------------------------------------
__global__ __launch_bounds__(512, 4) void blur_kernel(
    const float* __restrict__ p_ea, const float* __restrict__ p_soft,
    const float* __restrict__ p_int, const float* __restrict__ p_rot,
    const float* __restrict__ p_hard, float* __restrict__ out)
{
    GWDECL;
    extern __shared__ float smem[];
    float* const sB = smem;                 // 92*81 = 7452
    float* const sD = smem;                 // 78*67 = 5226 (alias; sB dead after V1)
    float* const sC = smem + 7452;          // 78*81 = 6318

    const int tid = threadIdx.x;
    const int img = blockIdx.z;
    const int ty0 = blockIdx.y * TILE;
    const int tx0 = blockIdx.x * TILE;

    const float eav = p_ea[0], sof = p_soft[0];
    const float itn = p_int[0], hrd = p_hard[0];
    float snt, cst;
    sincosf(p_rot[0] * 0.017453292519943295f, &snt, &cst);

    const float*  __restrict__ xin = g_x4  + (size_t)img * (HSZ * WSZ);
    const __half* __restrict__ hin = g_h1h + (size_t)img * (HSZ * WSZ);
    // needs rows ty0-14..ty0+77, cols tx0-7..tx0+70
    const bool interior = (ty0 >= 14) && (ty0 + 78 <= HSZ) && (tx0 >= 7) && (tx0 + 71 <= WSZ);

    // ---- phase 0: coalesced copy of H1 halo -> sB (fp16 -> fp32) ----
    if (interior) {
        const __half* __restrict__ base = hin + (ty0 - 14) * WSZ + (tx0 - 7);
        for (int p = tid; p < 92 * 78; p += 512) {
            int r = p / 78, c = p - r * 78;
            sB[r * 81 + c] = __half2float(__ldg(base + r * WSZ + c));
        }
    } else {
        for (int p = tid; p < 92 * 78; p += 512) {
            int r = p / 78, c = p - r * 78;
            int gy = ty0 - 14 + r, gx = tx0 - 7 + c;
            float v = 0.f;
            if ((unsigned)gy < HSZ && (unsigned)gx < WSZ)
                v = __half2float(__ldg(hin + gy * WSZ + gx));
            sB[r * 81 + c] = v;                 // H1 == 0 outside image (zero-pad)
        }
    }
    __syncthreads();

    // ---- V1 + LCE epilogue: sB -> sC. 468 thr: col=tid%78, 6 strips x 13 rows ----
    if (tid < 468) {
        int strip = tid / 78, ccol = tid - 78 * strip;
        int r0 = strip * 13;
        const float* b = &sB[r0 * 81 + ccol];
        float acc[13] = {};
        #pragma unroll
        for (int i = 0; i < 27; ++i) {          // rows r0..r0+26 <= 91, all real
            float v = b[i * 81];
            #pragma unroll
            for (int k = 0; k < 15; ++k) {
                int j = i - k;
                if (j >= 0 && j < 13) acc[j] = fmaf(v, GW[k], acc[j]);
            }
        }
        if (interior) {
            const float* __restrict__ ctr = xin + (ty0 - 7 + r0) * WSZ + (tx0 - 7 + ccol);
            #pragma unroll
            for (int j = 0; j < 13; ++j) {
                float a = __ldg(ctr + j * WSZ); // coalesced: lanes = consecutive cols
                sC[(r0 + j) * 81 + ccol] = fmaf(eav, a - acc[j], a);  // x + ea*(x - mean)
            }
        } else {
            #pragma unroll
            for (int j = 0; j < 13; ++j) {
                int rr = r0 + j;
                int gy = ty0 - 7 + rr, gx = tx0 - 7 + ccol;
                float val = 0.f;
                if ((unsigned)gy < HSZ && (unsigned)gx < WSZ) {
                    float a = __ldg(xin + gy * WSZ + gx);
                    val = fmaf(eav, a - acc[j], a);
                }
                sC[rr * 81 + ccol] = val;       // zero outside image = blur2 zero-pad
            }
        }
    }
    __syncthreads();

    // ---- H2: sC -> sD (aliases sB). row-fast lanes, 11 outputs/thread, window 25 ----
    if (tid < 468) {
        int r = tid % 78, seg = tid / 78;
        int c0 = seg * 11;
        const float* c = &sC[r * 81 + c0];
        float acc[11] = {};
        #pragma unroll
        for (int i = 0; i < 25; ++i) {
            float v = c[i];                     // junk cols 78..79 -> only discarded accs
            #pragma unroll
            for (int k = 0; k < 15; ++k) {
                int j = i - k;
                if (j >= 0 && j < 11) acc[j] = fmaf(v, GW[k], acc[j]);
            }
        }
        float* d = &sD[r * 67 + c0];
        #pragma unroll
        for (int j = 0; j < 11; ++j)
            if (c0 + j < 64) d[j] = acc[j];
    }
    __syncthreads();

    // ---- V2 + softness + gradient mask -> out. 64 cols x 8 strips x 8 rows ----
    {
        int strip = tid >> 6, cc = tid & 63;
        int r0 = strip * 8;
        const float* d = &sD[r0 * 67 + cc];
        float acc[8] = {};
        #pragma unroll
        for (int i = 0; i < 22; ++i) {          // rows r0..r0+21 <= 77, all real
            float v = d[i * 67];
            #pragma unroll
            for (int k = 0; k < 15; ++k) {
                int j = i - k;
                if (j >= 0 && j < 8) acc[j] = fmaf(v, GW[k], acc[j]);
            }
        }
        float* __restrict__ op = out + (size_t)img * (HSZ * WSZ);
        const float yscale = 2.f / (float)(HSZ - 1);
        const float xscale = 2.f / (float)(WSZ - 1);
        const float mc = 1.f - 0.5f * itn;      // factor = mc + md*tanh(-hrd*gr/2)
        const float md = -0.5f * itn;
        const int gx = tx0 + cc;
        const float xn = fmaf((float)gx, xscale, -1.f);
        #pragma unroll
        for (int j = 0; j < 8; ++j) {
            int gy = ty0 + r0 + j;
            float x5c = sC[(r0 + j + 7) * 81 + cc + 7];
            float v = sof * acc[j] + (1.f - sof) * x5c;        // softness blend
            float yn = fmaf((float)gy, yscale, -1.f);
            float gr = xn * cst + yn * snt;
            float fac = fmaf(md, tanh_approx(-0.5f * hrd * gr), mc);  // 1 - itn*sigmoid(-hrd*gr)
            v = fminf(fmaxf(v * fac, 0.f), 1.f);
            op[gy * WSZ + gx] = v;
        }
    }
}

extern "C" void kernel_launch(void* const* d_in, const int* in_sizes, int n_in,
                              void* d_out, int out_size) {
    (void)in_sizes; (void)n_in; (void)out_size;

    static const int SMEM_BYTES = (7452 + 6318) * 4;          // 55,080
    cudaFuncSetAttribute(blur_kernel, cudaFuncAttributeMaxDynamicSharedMemorySize, SMEM_BYTES);

    pointwise_h1_kernel<<<NIMG * HSZ, 256>>>(                 // one block per image row
        (const float*)d_in[0],  // x
        (const float*)d_in[1],  // gains
        (const float*)d_in[2],  // gamma
        (const float*)d_in[3],  // shadow_boost
        (const float*)d_in[4],  // highlight_reduce
        (const float*)d_in[5],  // brightness
        (const float*)d_in[6]); // contrast

    dim3 grid(WSZ / TILE, HSZ / TILE, NIMG);                  // 16 x 16 x 12 = 3072 CTAs
    blur_kernel<<<grid, 512, SMEM_BYTES>>>(
        (const float*)d_in[7],  // enhance_amount
        (const float*)d_in[8],  // softness
        (const float*)d_in[9],  // intensity
        (const float*)d_in[10], // rotation
        (const float*)d_in[11], // hardness
        (float*)d_out);
}

// round 14
// speedup vs baseline: 1.4134x; 1.3371x over previous
#include <cuda_runtime.h>
#include <cuda_fp16.h>
#include <math.h>

#define HSZ 1024
#define WSZ 1024
#define NIMG 12            // B*C = 4*3
#define TILE 64            // output tile (64x64), 512 threads
#define NPIX (NIMG * HSZ * WSZ)

// Scratch (static __device__ arrays = allowed). Both fp16 so the K2 working
// set (x4h 25MB + h1h 25MB + out 50MB = 100MB) fits the 126MB L2.
__device__ __half g_x4h[NPIX];   // pointwise-processed image
__device__ __half g_h1h[NPIX];   // horizontal 15-tap blur of x4

// ---------------------------------------------------------------------------
// Compile-time Gaussian weights (KSIZE=15, SIGMA=3) -> FFMA-imm literals.
// ---------------------------------------------------------------------------
__host__ __device__ constexpr double cexp_(double x) {
    double t = 1.0, s = 1.0;
    for (int i = 1; i < 60; ++i) { t *= x / i; s += t; }
    return s;
}
__host__ __device__ constexpr double gsum_() {
    double s = 0.0;
    for (int i = 0; i < 15; ++i) { double d = i - 7; s += cexp_(-d * d / 18.0); }
    return s;
}
__host__ __device__ constexpr float gw_(int k) {
    double d = k - 7; return (float)(cexp_(-d * d / 18.0) / gsum_());
}
#define GWDECL constexpr float GW[15] = {gw_(0), gw_(1), gw_(2),  gw_(3),  gw_(4),  \
    gw_(5),  gw_(6), gw_(7), gw_(8), gw_(9), gw_(10), gw_(11), gw_(12), gw_(13), gw_(14)}

__device__ __forceinline__ float tanh_approx(float x) {
    float y; asm("tanh.approx.f32 %0, %1;" : "=f"(y) : "f"(x));
    return y;
}

// ---------------------------------------------------------------------------
// K1: pointwise chain + horizontal blur H1, one block per image row.
//   256 threads x 4 px; x4 -> g_x4h (fp16), H1 -> g_h1h (fp16)
// ---------------------------------------------------------------------------
__global__ __launch_bounds__(256) void pointwise_h1_kernel(
    const float* __restrict__ x, const float* __restrict__ gains,
    const float* __restrict__ p_gamma, const float* __restrict__ p_sb,
    const float* __restrict__ p_hr, const float* __restrict__ p_br,
    const float* __restrict__ p_ct)
{
    GWDECL;
    __shared__ __align__(16) float sRow[1040];   // [8 zero | 1024 px | 8 zero]

    const int bx  = blockIdx.x;                  // img*1024 + row
    const int tid = threadIdx.x;
    const int ch  = (bx >> 10) % 3;

    const float gain = gains[ch];
    const float gam  = p_gamma[0];
    const float sbv  = p_sb[0], hrv = p_hr[0];
    const float shc  = -(sbv + hrv);
    const float brv  = p_br[0], ctv = p_ct[0];
    const float bc0  = 0.5f + brv;

    if (tid < 8) { sRow[tid] = 0.f; sRow[1032 + tid] = 0.f; }

    const int idx4 = bx * 256 + tid;             // float4 index (row-contiguous)
    float4 v4 = __ldg((const float4*)x + idx4);
    float* v = &v4.x;
    #pragma unroll
    for (int i = 0; i < 4; ++i) {
        float t = __powf(v[i] * gain, gam);                   // WB + gamma
        float hi = fmaf(tanh_approx((t - 0.5f) * 5.f), 0.5f, 0.5f);
        t = fmaf(shc, hi, t + sbv);                           // shadow/highlight
        t = fminf(fmaxf(t, 0.f), 1.f);
        t = fmaf(ctv, t - 0.5f, bc0);                         // brightness/contrast
        v[i] = fminf(fmaxf(t, 0.f), 1.f);
    }
    {   // store x4 as fp16 (one STG.64)
        __half2 a0 = __floats2half2_rn(v[0], v[1]);
        __half2 a1 = __floats2half2_rn(v[2], v[3]);
        uint2 u;
        u.x = *reinterpret_cast<unsigned*>(&a0);
        u.y = *reinterpret_cast<unsigned*>(&a1);
        *reinterpret_cast<uint2*>(g_x4h + 4 * (size_t)idx4) = u;
    }
    *(float4*)&sRow[8 + 4 * tid] = v4;           // full-precision row for H1
    __syncthreads();

    // window w[0..19] = sRow floats [4t .. 4t+19] = x4 cols [4t-8 .. 4t+11]
    float w[20];
    const float4* sv = (const float4*)sRow;
    #pragma unroll
    for (int i = 0; i < 5; ++i) {
        float4 q = sv[tid + i];                  // conflict-free LDS.128
        w[4 * i + 0] = q.x; w[4 * i + 1] = q.y;
        w[4 * i + 2] = q.z; w[4 * i + 3] = q.w;
    }
    float o[4];
    #pragma unroll
    for (int j = 0; j < 4; ++j) {                // out col c = 4t+j needs x4[c-7..c+7] = w[j+1..j+15]
        float a = 0.f;
        #pragma unroll
        for (int k = 0; k < 15; ++k) a = fmaf(w[j + 1 + k], GW[k], a);
        o[j] = a;
    }
    {
        __half2 h0 = __floats2half2_rn(o[0], o[1]);
        __half2 h1 = __floats2half2_rn(o[2], o[3]);
        uint2 u;
        u.x = *reinterpret_cast<unsigned*>(&h0);
        u.y = *reinterpret_cast<unsigned*>(&h1);
        *reinterpret_cast<uint2*>(g_h1h + 4 * (size_t)idx4) = u;
    }
}

// ---------------------------------------------------------------------------
// K2: remaining cascade per 64x64 tile. 512 threads, smem 46,176 B, regs
// capped at 32 -> 4 CTAs/SM (2048 thr, full RF).
//   V1+LCE: read g_h1h DIRECTLY from global (consecutive lanes = consecutive
//           columns -> coalesced, L2-resident) -> sC [78x78]; LCE centers
//           from g_x4h (also coalesced).
//   H2: sC -> sD [78x64]   (row-fast lanes, conflict-free: 81%32=17)
//   V2+softness+mask -> out
// ---------------------------------------------------------------------------
__global__ __launch_bounds__(512, 4) void blur_kernel(
    const float* __restrict__ p_ea, const float* __restrict__ p_soft,
    const float* __restrict__ p_int, const float* __restrict__ p_rot,
    const float* __restrict__ p_hard, float* __restrict__ out)
{
    GWDECL;
    extern __shared__ float smem[];
    float* const sC = smem;                 // 78*81 = 6318
    float* const sD = smem + 6318;          // 78*67 = 5226

    const int tid = threadIdx.x;
    const int img = blockIdx.z;
    const int ty0 = blockIdx.y * TILE;
    const int tx0 = blockIdx.x * TILE;

    const float eav = p_ea[0], sof = p_soft[0];
    const float itn = p_int[0], hrd = p_hard[0];
    float snt, cst;
    sincosf(p_rot[0] * 0.017453292519943295f, &snt, &cst);

    const __half* __restrict__ x4 = g_x4h + (size_t)img * (HSZ * WSZ);
    const __half* __restrict__ h1 = g_h1h + (size_t)img * (HSZ * WSZ);
    // needs rows ty0-14..ty0+77, cols tx0-7..tx0+70
    const bool interior = (ty0 >= 14) && (ty0 + 78 <= HSZ) && (tx0 >= 7) && (tx0 + 71 <= WSZ);

    // ---- V1 + LCE epilogue: global h1 -> sC. 468 thr: col=tid%78, 6 strips x 13 rows ----
    if (tid < 468) {
        int strip = tid / 78, ccol = tid - 78 * strip;
        int r0 = strip * 13;
        float acc[13] = {};
        if (interior) {
            const __half* __restrict__ hp = h1 + (ty0 - 14 + r0) * WSZ + (tx0 - 7 + ccol);
            #pragma unroll
            for (int i = 0; i < 27; ++i) {      // rows r0..r0+26 <= 91, all in image
                float v = __half2float(__ldg(hp + i * WSZ));   // coalesced halfs
                #pragma unroll
                for (int k = 0; k < 15; ++k) {
                    int j = i - k;
                    if (j >= 0 && j < 13) acc[j] = fmaf(v, GW[k], acc[j]);
                }
            }
            const __half* __restrict__ ctr = x4 + (ty0 - 7 + r0) * WSZ + (tx0 - 7 + ccol);
            #pragma unroll
            for (int j = 0; j < 13; ++j) {
                float a = __half2float(__ldg(ctr + j * WSZ));
                sC[(r0 + j) * 81 + ccol] = fmaf(eav, a - acc[j], a);  // x + ea*(x - mean)
            }
        } else {
            int gx = tx0 - 7 + ccol;
            bool colok = (unsigned)gx < WSZ;
            #pragma unroll
            for (int i = 0; i < 27; ++i) {
                int gy = ty0 - 14 + r0 + i;
                float v = (colok && (unsigned)gy < HSZ)
                          ? __half2float(__ldg(h1 + gy * WSZ + gx)) : 0.f;
                #pragma unroll
                for (int k = 0; k < 15; ++k) {
                    int j = i - k;
                    if (j >= 0 && j < 13) acc[j] = fmaf(v, GW[k], acc[j]);
                }
            }
            #pragma unroll
            for (int j = 0; j < 13; ++j) {
                int gy = ty0 - 7 + r0 + j;
                float val = 0.f;
                if (colok && (unsigned)gy < HSZ) {
                    float a = __half2float(__ldg(x4 + gy * WSZ + gx));
                    val = fmaf(eav, a - acc[j], a);
                }
                sC[(r0 + j) * 81 + ccol] = val; // zero outside image = blur2 zero-pad
            }
        }
    }
    __syncthreads();

    // ---- H2: sC -> sD. row-fast lanes, 11 outputs/thread, window 25 ----
    if (tid < 468) {
        int r = tid % 78, seg = tid / 78;
        int c0 = seg * 11;
        const float* c = &sC[r * 81 + c0];
        float acc[11] = {};
        #pragma unroll
        for (int i = 0; i < 25; ++i) {
            float v = c[i];                     // junk cols 78..79 -> only discarded accs
            #pragma unroll
            for (int k = 0; k < 15; ++k) {
                int j = i - k;
                if (j >= 0 && j < 11) acc[j] = fmaf(v, GW[k], acc[j]);
            }
        }
        float* d = &sD[r * 67 + c0];
        #pragma unroll
        for (int j = 0; j < 11; ++j)
            if (c0 + j < 64) d[j] = acc[j];
    }
    __syncthreads();

    // ---- V2 + softness + gradient mask -> out. 64 cols x 8 strips x 8 rows ----
    {
        int strip = tid >> 6, cc = tid & 63;
        int r0 = strip * 8;
        const float* d = &sD[r0 * 67 + cc];
        float acc[8] = {};
        #pragma unroll
        for (int i = 0; i < 22; ++i) {          // rows r0..r0+21 <= 77, all real
            float v = d[i * 67];
            #pragma unroll
            for (int k = 0; k < 15; ++k) {
                int j = i - k;
                if (j >= 0 && j < 8) acc[j] = fmaf(v, GW[k], acc[j]);
            }
        }
        float* __restrict__ op = out + (size_t)img * (HSZ * WSZ);
        const float yscale = 2.f / (float)(HSZ - 1);
        const float xscale = 2.f / (float)(WSZ - 1);
        const float mc = 1.f - 0.5f * itn;      // factor = mc + md*tanh(-hrd*gr/2)
        const float md = -0.5f * itn;
        const int gx = tx0 + cc;
        const float xn = fmaf((float)gx, xscale, -1.f);
        #pragma unroll
        for (int j = 0; j < 8; ++j) {
            int gy = ty0 + r0 + j;
            float x5c = sC[(r0 + j + 7) * 81 + cc + 7];
            float v = sof * acc[j] + (1.f - sof) * x5c;        // softness blend
            float yn = fmaf((float)gy, yscale, -1.f);
            float gr = xn * cst + yn * snt;
            float fac = fmaf(md, tanh_approx(-0.5f * hrd * gr), mc);  // 1 - itn*sigmoid(-hrd*gr)
            v = fminf(fmaxf(v * fac, 0.f), 1.f);
            op[gy * WSZ + gx] = v;
        }
    }
}

extern "C" void kernel_launch(void* const* d_in, const int* in_sizes, int n_in,
                              void* d_out, int out_size) {
    (void)in_sizes; (void)n_in; (void)out_size;

    static const int SMEM_BYTES = (6318 + 5226) * 4;          // 46,176
    cudaFuncSetAttribute(blur_kernel, cudaFuncAttributeMaxDynamicSharedMemorySize, SMEM_BYTES);

    pointwise_h1_kernel<<<NIMG * HSZ, 256>>>(                 // one block per image row
        (const float*)d_in[0],  // x
        (const float*)d_in[1],  // gains
        (const float*)d_in[2],  // gamma
        (const float*)d_in[3],  // shadow_boost
        (const float*)d_in[4],  // highlight_reduce
        (const float*)d_in[5],  // brightness
        (const float*)d_in[6]); // contrast

    dim3 grid(WSZ / TILE, HSZ / TILE, NIMG);                  // 16 x 16 x 12 = 3072 CTAs
    blur_kernel<<<grid, 512, SMEM_BYTES>>>(
        (const float*)d_in[7],  // enhance_amount
        (const float*)d_in[8],  // softness
        (const float*)d_in[9],  // intensity
        (const float*)d_in[10], // rotation
        (const float*)d_in[11], // hardness
        (float*)d_out);
}